// round 9
// baseline (speedup 1.0000x reference)
#include <cuda_runtime.h>

#define NMAPS   128      // 4*32
#define H       480
#define W       640
#define GRID_N  10
#define CH      48
#define CW      64
#define CELLS   100
#define INTMAX_ 0x7fffffff

__device__ float    g_cand_score[NMAPS * CELLS];
__device__ int      g_cand_gr[NMAPS * CELLS];
__device__ int      g_cand_gc[NMAPS * CELLS];
__device__ unsigned g_count[NMAPS];   // never reset: mod-100 detects last arrival per map per launch

// larger value wins; exact tie -> smaller flat index (first occurrence, like jnp.argmax)
__device__ __forceinline__ void combine(float& bv, int& bi, float v, int i) {
    if (v > bv || (v == bv && i < bi)) { bv = v; bi = i; }
}
__device__ __forceinline__ float vmax4(float4 v) {
    return fmaxf(fmaxf(v.x, v.y), fmaxf(v.z, v.w));
}
__device__ __forceinline__ int selidx(float4 v, float m, int f) {
    int a = (v.x == m) ? f     : INTMAX_;
    int b = (v.y == m) ? f + 1 : INTMAX_;
    int c = (v.z == m) ? f + 2 : INTMAX_;
    int d = (v.w == m) ? f + 3 : INTMAX_;
    return min(min(a, b), min(c, d));
}

// One CTA covers a 2x2 block of cells: 96 rows x 128 cols contiguous.
// grid = NMAPS * 5 * 5 = 3200, block = 256. 12 independent float4 loads per thread.
__global__ __launch_bounds__(256)
void quadcell_argmax_topk_kernel(const float* __restrict__ s, float* __restrict__ out, int top_n) {
    const int blk  = blockIdx.x;                 // map*25 + ci2*5 + cj2
    const int map  = blk / 25;
    const int rem  = blk - map * 25;
    const int ci2  = rem / 5;                    // covers cell rows 2*ci2, 2*ci2+1
    const int cj2  = rem - ci2 * 5;              // covers cell cols 2*cj2, 2*cj2+1

    const float* mbase = s + (size_t)map * (H * W);
    const float4* base4 = reinterpret_cast<const float4*>(mbase)
                        + (size_t)(ci2 * 96) * (W / 4) + cj2 * 32;   // 128 cols = 32 float4

    const int tid  = threadIdx.x;
    const int w    = tid >> 5;     // warp 0..7
    const int lq   = tid & 31;     // float4 col within 128-col block
    const int half = lq >> 4;      // 0 -> left cell, 1 -> right cell
    const int ccol = lq & 15;      // float4 col within the cell

    const float4* p = base4 + w * (W / 4) + lq;
    const int rowstep = 8 * (W / 4);

    // 12 independent loads: rows w+8*it, it=0..11 (0..5 top cell-row, 6..11 bottom)
    float4 v[12];
    #pragma unroll
    for (int it = 0; it < 12; ++it) v[it] = p[it * rowstep];

    // per-vector maxes, then two accumulator trees (top / bottom cell)
    float m[12];
    #pragma unroll
    for (int it = 0; it < 12; ++it) m[it] = vmax4(v[it]);

    float tT = fmaxf(fmaxf(fmaxf(m[0], m[1]), fmaxf(m[2], m[3])), fmaxf(m[4], m[5]));
    float tB = fmaxf(fmaxf(fmaxf(m[6], m[7]), fmaxf(m[8], m[9])), fmaxf(m[10], m[11]));

    // flat idx within a cell: local_row*64 + ccol*4 + k ; local_row = w + 8*it'
    int biT = INTMAX_, biB = INTMAX_;
    #pragma unroll
    for (int it = 0; it < 6; ++it) {
        const int fb = (w + 8 * it) * 64 + ccol * 4;
        biT = min(biT, selidx(v[it],     tT, fb));
        biB = min(biB, selidx(v[it + 6], tB, fb));
    }
    float bvT = tT, bvB = tB;

    // half-warp (width 16) reduce both accumulators
    #pragma unroll
    for (int off = 8; off > 0; off >>= 1) {
        float ovT = __shfl_down_sync(0xffffffffu, bvT, off, 16);
        int   oiT = __shfl_down_sync(0xffffffffu, biT, off, 16);
        float ovB = __shfl_down_sync(0xffffffffu, bvB, off, 16);
        int   oiB = __shfl_down_sync(0xffffffffu, biB, off, 16);
        combine(bvT, biT, ovT, oiT);
        combine(bvB, biB, ovB, oiB);
    }

    __shared__ float sv[2][2][8];     // [vert][half][warp]
    __shared__ int   si[2][2][8];
    __shared__ int   s_last;
    if (tid == 0) s_last = 0;
    if (ccol == 0) {
        sv[0][half][w] = bvT; si[0][half][w] = biT;
        sv[1][half][w] = bvB; si[1][half][w] = biB;
    }
    __syncthreads();

    // threads 0..3 finalize the four cells: vert = tid>>1, hh = tid&1
    if (tid < 4) {
        const int vert = tid >> 1;
        const int hh   = tid & 1;
        float fv = sv[vert][hh][0];
        int   fi = si[vert][hh][0];
        #pragma unroll
        for (int k = 1; k < 8; ++k) combine(fv, fi, sv[vert][hh][k], si[vert][hh][k]);

        const int ci   = ci2 * 2 + vert;
        const int cj   = cj2 * 2 + hh;
        const int cidx = ci * GRID_N + cj;
        int lr2 = fi >> 6;
        int lc2 = fi & 63;
        int gr = ci * CH + lr2; gr = gr < 1 ? 1 : (gr > H - 2 ? H - 2 : gr);
        int gc = cj * CW + lc2; gc = gc < 1 ? 1 : (gc > W - 2 ? W - 2 : gc);
        // score is read at the CLAMPED coordinate (faithful to the reference)
        const int cell = map * CELLS + cidx;
        g_cand_score[cell] = mbase[gr * W + gc];
        g_cand_gr[cell]    = gr;
        g_cand_gc[cell]    = gc;
        __threadfence();                       // release: publish before counting
        unsigned old = atomicAdd(&g_count[map], 1u);
        if ((old % (unsigned)CELLS) == (unsigned)(CELLS - 1)) s_last = 1;
    }
    __syncthreads();

    // ---- the CTA that published the map's 100th candidate does the top-k ----
    if (s_last) {
        __shared__ unsigned long long keys[CELLS];
        __shared__ int   sgr[CELLS], sgc[CELLS];
        __shared__ float ssc[CELLS];

        __threadfence();                       // acquire
        if (tid < CELLS) {
            float sc = __ldcg(&g_cand_score[map * CELLS + tid]);
            int   gr = __ldcg(&g_cand_gr[map * CELLS + tid]);
            int   gc = __ldcg(&g_cand_gc[map * CELLS + tid]);
            unsigned u = __float_as_uint(sc);
            unsigned mono = (u & 0x80000000u) ? ~u : (u | 0x80000000u);
            keys[tid] = ((unsigned long long)mono << 32) | (unsigned)(CELLS - 1 - tid);
            sgr[tid] = gr; sgc[tid] = gc; ssc[tid] = sc;
        }
        __syncthreads();
        if (tid < CELLS) {
            const unsigned long long mk = keys[tid];
            int rank = 0;
            #pragma unroll 10
            for (int jj = 0; jj < CELLS; ++jj) rank += (keys[jj] > mk);
            if (rank < top_n) {
                const int o = map * top_n + rank;
                out[o]                     = (float)sgr[tid];   // x = row indices
                out[NMAPS * top_n + o]     = (float)sgc[tid];   // y = col indices
                out[2 * NMAPS * top_n + o] = ssc[tid];          // scores
            }
        }
    }
}

extern "C" void kernel_launch(void* const* d_in, const int* in_sizes, int n_in,
                              void* d_out, int out_size) {
    const float* s = (const float*)d_in[0];
    int top_n = out_size / (3 * NMAPS);
    quadcell_argmax_topk_kernel<<<NMAPS * 25, 256>>>(s, (float*)d_out, top_n);
}